// round 10
// baseline (speedup 1.0000x reference)
#include <cuda_runtime.h>
#include <math.h>

// Problem constants
#define BB 64
#define NN 8732
#define CC 21
#define KCAND 200
#define MAXPC 20
#define MAXTOT 20
#define FULLM 0xffffffffu

#define CAP   512               // per-(b,c) candidate list capacity
#define TH_C  0.96f             // collect threshold, classes >= 1 (R9-proven)
#define TH_0  0.92f             // collect threshold, class 0      (R9-proven)

#define TILE 128
#define NTILES ((NN + TILE - 1) / TILE)   // 69
#define SLP 129                           // padded smem pitch

// Scratch (static device globals: allowed; no runtime allocation)
__device__ float4             g_boxes[BB * NN];        // decoded boxes
__device__ unsigned char      g_mask[BB * NN];         // argmax != 0 (fallback)
__device__ unsigned long long g_cand[(size_t)BB * CC * CAP]; // (score<<32)|n
__device__ int                g_cnt[BB * CC];
__device__ float              g_cls_scores[BB * CC * MAXPC]; // sorted desc
__device__ float4             g_cls_boxes[BB * CC * MAXPC];

// ---------------------------------------------------------------------------
// Kernel 0: zero the per-(b,c) candidate counters (graph replays need this)
// ---------------------------------------------------------------------------
__global__ void init_kernel() {
    int i = blockIdx.x * blockDim.x + threadIdx.x;
    if (i < BB * CC) g_cnt[i] = 0;
}

// ---------------------------------------------------------------------------
// Kernel A (R9 tile structure, measured 24us): decode + argmax mask +
// direct candidate push (replaces the 47MB transposed score write).
// ---------------------------------------------------------------------------
__global__ __launch_bounds__(TILE) void decode_kernel(
        const float* __restrict__ deltas,
        const float* __restrict__ labels,
        const float* __restrict__ anchors) {
    const int b    = blockIdx.x / NTILES;
    const int tile = blockIdx.x % NTILES;
    const int n0   = tile * TILE;
    const int cnt  = min(TILE, NN - n0);
    const int t    = threadIdx.x;

    __shared__ float sl[CC * SLP];

    const float* Lb  = labels + ((size_t)b * NN + n0) * CC;
    const int    tot = cnt * CC;
    for (int idx = t; idx < tot; idx += TILE) {
        int i = idx / CC;
        int c = idx - i * CC;
        sl[c * SLP + i] = Lb[idx];
    }
    __syncthreads();

    if (t < cnt) {
        // argmax over 21 classes (first-occurrence ties, like jnp.argmax)
        float best = sl[t];
        int   bi   = 0;
#pragma unroll
        for (int c = 1; c < CC; c++) {
            float v = sl[c * SLP + t];
            if (v > best) { best = v; bi = c; }
        }
        const bool masked = (bi != 0);
        const int  n      = n0 + t;
        g_mask[(size_t)b * NN + n] = masked ? 1 : 0;

        // decode box
        float4 a = __ldg(((const float4*)anchors) + n);
        float4 d = __ldg(((const float4*)deltas) + (size_t)b * NN + n);
        d.x *= 0.1f; d.y *= 0.1f; d.z *= 0.2f; d.w *= 0.2f;

        float ah  = a.z - a.x;
        float aw  = a.w - a.y;
        float acy = a.x + 0.5f * ah;
        float acx = a.y + 0.5f * aw;
        float cy  = d.x * ah + acy;
        float cx  = d.y * aw + acx;
        float h   = expf(d.z) * ah;
        float w   = expf(d.w) * aw;

        g_boxes[(size_t)b * NN + n] = make_float4(cy - 0.5f * h, cx - 0.5f * w,
                                                  cy + 0.5f * h, cx + 0.5f * w);

        // Candidate push (rare: ~4% of (anchor,class) pairs)
        if (masked) {
#pragma unroll
            for (int c = 0; c < CC; c++) {
                const float th = (c == 0) ? TH_0 : TH_C;
                float s = sl[c * SLP + t];
                if (s >= th) {
                    int p = atomicAdd(&g_cnt[b * CC + c], 1);
                    if (p < CAP) {
                        g_cand[(size_t)(b * CC + c) * CAP + p] =
                            ((unsigned long long)__float_as_uint(s) << 32)
                            | (unsigned)n;
                    }
                }
            }
        }
    }
}

// ---------------------------------------------------------------------------
// IoU, exactly mirroring the reference fp32 formula
// ---------------------------------------------------------------------------
__device__ __forceinline__ float iou_f(float4 A, float4 B2) {
    float areaA = (A.z - A.x) * (A.w - A.y);
    float areaB = (B2.z - B2.x) * (B2.w - B2.y);
    float ih = fminf(A.z, B2.z) - fmaxf(A.x, B2.x); ih = fmaxf(ih, 0.0f);
    float iw = fminf(A.w, B2.w) - fmaxf(A.y, B2.y); iw = fmaxf(iw, 0.0f);
    float inter = ih * iw;
    return inter / (areaA + areaB - inter + 1e-8f);
}

// key pack: [score bits:32 | (16383-n):14 | slot:9]  (desc sort => score desc,
// n asc on ties, exact jax top_k stable order; slot survives sorting)
__device__ __forceinline__ unsigned long long pack_key(float s, unsigned n,
                                                       unsigned slot) {
    return ((unsigned long long)__float_as_uint(s) << 32)
         | ((unsigned long long)((16383u - n) & 0x3FFFu) << 9)
         | (unsigned long long)(slot & 0x1FFu);
}

// Warp-register bitonic sort of 32 u64 keys, descending; no barriers.
__device__ __forceinline__ unsigned long long warpsort32_desc(
        unsigned long long key, int lane) {
#pragma unroll
    for (int k = 2; k <= 32; k <<= 1) {
#pragma unroll
        for (int j = k >> 1; j >= 1; j >>= 1) {
            unsigned long long other = __shfl_xor_sync(FULLM, key, j);
            bool dd   = ((lane & k) == 0);
            bool low  = ((lane & j) == 0);
            bool wmax = (dd == low);
            key = wmax ? (key > other ? key : other)
                       : (key < other ? key : other);
        }
    }
    return key;
}

// ---------------------------------------------------------------------------
// Kernel B: per-(b,c): load prebuilt candidates -> 16 warp-sorted runs ->
// single-warp 16-way merge-pop fused with greedy NMS. 256 threads per block.
// ---------------------------------------------------------------------------
__global__ __launch_bounds__(256) void nms_kernel(const float* __restrict__ labels) {
    const int bc   = blockIdx.x;
    const int b    = bc / CC;
    const int c    = bc % CC;
    const int tid  = threadIdx.x;
    const int lane = tid & 31;
    const int wid  = tid >> 5;

    __shared__ unsigned long long sk[512];
    __shared__ float4             sbox[512];
    __shared__ int                hist[1024];     // fallback only
    __shared__ int                s_count, s_cut;

    const int cnt = g_cnt[bc];
    int mn;

    if (cnt >= KCAND && cnt <= CAP) {
        // Fast path: list is a provable superset of the exact top-200
        const unsigned long long* Cl = g_cand + (size_t)bc * CAP;
        for (int i = tid; i < 512; i += 256) {
            unsigned long long kk = 0ULL;
            if (i < cnt) {
                unsigned long long raw = Cl[i];
                kk = pack_key(__uint_as_float((unsigned)(raw >> 32)),
                              (unsigned)(raw & 0xFFFFFFFFu), (unsigned)i);
            }
            sk[i] = kk;
        }
        mn = cnt;
    } else {
        // Exact fallback (statistically never taken): histogram two-pass on
        // raw labels (strided) + mask.
        for (int i = tid; i < 1024; i += 256) hist[i] = 0;
        if (tid == 0) s_count = 0;
        __syncthreads();

        const float*         Lcol = labels + (size_t)b * NN * CC + c;
        const unsigned char* Mb   = g_mask + (size_t)b * NN;

        for (int n = tid; n < NN; n += 256) {
            if (Mb[n]) {
                float s = Lcol[(size_t)n * CC];
                if (s > 0.0f)
                    atomicAdd(&hist[min((int)(s * 1024.0f), 1023)], 1);
            }
        }
        __syncthreads();
        if (tid == 0) {
            int cum = 0, cut = 0;
            for (int bin = 1023; bin >= 0; bin--) {
                cum += hist[bin];
                if (cum >= KCAND) { cut = bin; break; }
            }
            s_cut = cut;
        }
        __syncthreads();
        const int fcut = s_cut;
        for (int n = tid; n < NN; n += 256) {
            if (Mb[n]) {
                float s = Lcol[(size_t)n * CC];
                if (s > 0.0f && min((int)(s * 1024.0f), 1023) >= fcut) {
                    int p = atomicAdd(&s_count, 1);
                    if (p < 512)
                        sk[p] = pack_key(s, (unsigned)n, (unsigned)p);
                }
            }
        }
        __syncthreads();
        mn = min(s_count, 512);
        for (int i = mn + tid; i < 512; i += 256) sk[i] = 0ULL;
    }
    __syncthreads();
    mn = min(mn, 512);

    // Prefetch boxes (slot-indexed) + 16 barrier-free warp sorts
    unsigned long long k1 = sk[tid];
    unsigned long long k2 = sk[tid + 256];
    if (tid < mn) {
        unsigned n = 16383u - (unsigned)((k1 >> 9) & 0x3FFFu);
        sbox[tid] = g_boxes[(size_t)b * NN + n];
    }
    if (tid + 256 < mn) {
        unsigned n = 16383u - (unsigned)((k2 >> 9) & 0x3FFFu);
        sbox[tid + 256] = g_boxes[(size_t)b * NN + n];
    }
    k1 = warpsort32_desc(k1, lane);
    k2 = warpsort32_desc(k2, lane);
    sk[tid]       = k1;
    sk[tid + 256] = k2;
    __syncthreads();

    // Warp 0: 16-way merge-pop fused with greedy NMS (exact top-200 order)
    if (wid == 0) {
        const int outbase = bc * MAXPC;
        int    head   = 0;
        int    kc     = 0;
        int    pops   = 0;
        const int maxpops = min(mn, KCAND);
        float4 mykept = make_float4(0.f, 0.f, 0.f, 0.f);

        while (pops < maxpops && kc < MAXPC) {
            unsigned long long hk = 0ULL;
            if (lane < 16 && head < 32) hk = sk[lane * 32 + head];
            // butterfly argmax (keys unique; 0 = exhausted)
            unsigned long long bk = hk;
            int bl = lane;
#pragma unroll
            for (int off = 16; off >= 1; off >>= 1) {
                unsigned long long ok = __shfl_xor_sync(FULLM, bk, off);
                int                ol = __shfl_xor_sync(FULLM, bl, off);
                if (ok > bk) { bk = ok; bl = ol; }
            }
            if (bk == 0ULL) break;
            if (lane == bl) head++;
            pops++;

            float s = __uint_as_float((unsigned)(bk >> 32));
            if (s <= 0.5f) break;               // sorted: all later smaller
            int slot = (int)(bk & 0x1FFu);
            float4 cb = sbox[slot];             // smem broadcast

            bool ov = (lane < kc) && (iou_f(mykept, cb) > 0.5f);
            if (!__ballot_sync(FULLM, ov)) {
                if (lane == kc) mykept = cb;
                if (lane == 0) {
                    g_cls_scores[outbase + kc] = s;
                    g_cls_boxes[outbase + kc]  = cb;
                }
                kc++;
            }
        }
        if (lane < MAXPC && lane >= kc) {
            g_cls_scores[outbase + lane] = 0.0f;
            g_cls_boxes[outbase + lane]  = make_float4(0.f, 0.f, 0.f, 0.f);
        }
    }
}

// ---------------------------------------------------------------------------
// Kernel C (R9-proven): per-batch top-20 via 21-way merge-pop of the
// already-sorted per-class lists. One warp per batch; 8 warps per block.
// ---------------------------------------------------------------------------
__global__ __launch_bounds__(256) void merge_kernel(float* __restrict__ out) {
    const int wid  = threadIdx.x >> 5;
    const int lane = threadIdx.x & 31;
    const int b    = blockIdx.x * 8 + wid;

    __shared__ float ssc[8][CC * MAXPC];

    for (int i = lane; i < CC * MAXPC; i += 32)
        ssc[wid][i] = g_cls_scores[b * CC * MAXPC + i];
    __syncwarp();

    int   head  = 0;
    int   myfi  = 0;
    float myval = 0.0f;
    bool  mywin = false;

#pragma unroll
    for (int p = 0; p < MAXTOT; p++) {
        // key: [score bits:32 | (1023-flat):16]; desc => score desc, flat asc
        unsigned long long k = 0ULL;
        if (lane < CC && head < MAXPC) {
            int   fi = lane * MAXPC + head;
            float s  = ssc[wid][fi];
            k = ((unsigned long long)__float_as_uint(s) << 16)
                | (unsigned long long)(1023 - fi);
        }
        unsigned long long bk = k;
#pragma unroll
        for (int off = 16; off >= 1; off >>= 1) {
            unsigned long long ok = __shfl_xor_sync(FULLM, bk, off);
            if (ok > bk) bk = ok;
        }
        int   fi = 1023 - (int)(bk & 0xFFFFu);
        float s  = __uint_as_float((unsigned)(bk >> 16));
        if (lane == fi / MAXPC) head++;         // winner class advances
        if (lane == p) { myfi = fi; myval = s; mywin = true; }
    }

    if (lane < MAXTOT && mywin) {
        float  s  = myval;
        float4 bx = make_float4(0.f, 0.f, 0.f, 0.f);
        float  lab = 0.0f;
        if (s > 0.0f) {
            bx = g_cls_boxes[b * CC * MAXPC + myfi];
            bx.x = fminf(fmaxf(bx.x, 0.0f), 1.0f);
            bx.y = fminf(fmaxf(bx.y, 0.0f), 1.0f);
            bx.z = fminf(fmaxf(bx.z, 0.0f), 1.0f);
            bx.w = fminf(fmaxf(bx.w, 0.0f), 1.0f);
            lab = (float)(myfi / MAXPC);
        }
        // Output layout: boxes [B,20,4] | vals [B,20] | labels [B,20]
        float* ob = out + (size_t)b * MAXTOT * 4;
        float* ov = out + (size_t)BB * MAXTOT * 4 + (size_t)b * MAXTOT;
        float* ol = out + (size_t)BB * MAXTOT * 4 + (size_t)BB * MAXTOT
                        + (size_t)b * MAXTOT;
        ob[lane * 4 + 0] = bx.x;
        ob[lane * 4 + 1] = bx.y;
        ob[lane * 4 + 2] = bx.z;
        ob[lane * 4 + 3] = bx.w;
        ov[lane] = s;
        ol[lane] = lab;
    }
}

// ---------------------------------------------------------------------------
extern "C" void kernel_launch(void* const* d_in, const int* in_sizes, int n_in,
                              void* d_out, int out_size) {
    const float* deltas  = (const float*)d_in[0];  // (64, 8732, 4)
    const float* labels  = (const float*)d_in[1];  // (64, 8732, 21)
    const float* anchors = (const float*)d_in[2];  // (8732, 4)
    float* out = (float*)d_out;

    init_kernel<<<(BB * CC + 255) / 256, 256>>>();
    decode_kernel<<<BB * NTILES, TILE>>>(deltas, labels, anchors);
    nms_kernel<<<BB * CC, 256>>>(labels);
    merge_kernel<<<BB / 8, 256>>>(out);
}

// round 11
// speedup vs baseline: 1.3568x; 1.3568x over previous
#include <cuda_runtime.h>
#include <math.h>

// Problem constants
#define BB 64
#define NN 8732
#define NN4 (NN / 4)            // 2183
#define CC 21
#define KCAND 200
#define MAXPC 20
#define MAXTOT 20
#define FULLM 0xffffffffu

#define TH_C  0.96f             // collect threshold, classes >= 1
#define TH_0  0.92f             // collect threshold, class 0

#define TILE 128
#define NTILES ((NN + TILE - 1) / TILE)   // 69
#define SLP 129                           // padded smem pitch

// Scratch (static device globals: allowed; no runtime allocation)
__device__ float4 g_boxes[BB * NN];                  // decoded boxes
__device__ float4 g_scoresT4[(size_t)BB * CC * NN4]; // masked scores, [b][c][n/4]
__device__ float  g_cls_scores[BB * CC * MAXPC];     // per-class kept, sorted desc
__device__ float4 g_cls_boxes[BB * CC * MAXPC];

// ---------------------------------------------------------------------------
// Kernel A (measured 24.1us, unchanged from R9): decode + argmax mask +
// transposed masked-score write
// ---------------------------------------------------------------------------
__global__ __launch_bounds__(TILE) void decode_kernel(
        const float* __restrict__ deltas,
        const float* __restrict__ labels,
        const float* __restrict__ anchors) {
    const int b    = blockIdx.x / NTILES;
    const int tile = blockIdx.x % NTILES;
    const int n0   = tile * TILE;
    const int cnt  = min(TILE, NN - n0);
    const int t    = threadIdx.x;

    __shared__ float         sl[CC * SLP];
    __shared__ unsigned char sm[TILE];

    const float* Lb  = labels + ((size_t)b * NN + n0) * CC;
    const int    tot = cnt * CC;
    for (int idx = t; idx < tot; idx += TILE) {
        int i = idx / CC;
        int c = idx - i * CC;
        sl[c * SLP + i] = Lb[idx];
    }
    __syncthreads();

    if (t < cnt) {
        float best = sl[t];
        int   bi   = 0;
#pragma unroll
        for (int c = 1; c < CC; c++) {
            float v = sl[c * SLP + t];
            if (v > best) { best = v; bi = c; }
        }
        sm[t] = (bi != 0) ? 1 : 0;

        const int n = n0 + t;
        float4 a = __ldg(((const float4*)anchors) + n);
        float4 d = __ldg(((const float4*)deltas) + (size_t)b * NN + n);
        d.x *= 0.1f; d.y *= 0.1f; d.z *= 0.2f; d.w *= 0.2f;

        float ah  = a.z - a.x;
        float aw  = a.w - a.y;
        float acy = a.x + 0.5f * ah;
        float acx = a.y + 0.5f * aw;
        float cy  = d.x * ah + acy;
        float cx  = d.y * aw + acx;
        float h   = expf(d.z) * ah;
        float w   = expf(d.w) * aw;

        g_boxes[(size_t)b * NN + n] = make_float4(cy - 0.5f * h, cx - 0.5f * w,
                                                  cy + 0.5f * h, cx + 0.5f * w);
    }
    __syncthreads();

    const int g4 = cnt >> 2;
    for (int idx = t; idx < CC * g4; idx += TILE) {
        const int c  = idx / g4;
        const int i4 = idx - c * g4;
        float4 v;
        const int ib = i4 * 4;
        v.x = sm[ib + 0] ? sl[c * SLP + ib + 0] : 0.0f;
        v.y = sm[ib + 1] ? sl[c * SLP + ib + 1] : 0.0f;
        v.z = sm[ib + 2] ? sl[c * SLP + ib + 2] : 0.0f;
        v.w = sm[ib + 3] ? sl[c * SLP + ib + 3] : 0.0f;
        g_scoresT4[((size_t)b * CC + c) * NN4 + (n0 >> 2) + i4] = v;
    }
}

// ---------------------------------------------------------------------------
// IoU, exactly mirroring the reference fp32 formula
// ---------------------------------------------------------------------------
__device__ __forceinline__ float iou_f(float4 A, float4 B2) {
    float areaA = (A.z - A.x) * (A.w - A.y);
    float areaB = (B2.z - B2.x) * (B2.w - B2.y);
    float ih = fminf(A.z, B2.z) - fmaxf(A.x, B2.x); ih = fmaxf(ih, 0.0f);
    float iw = fminf(A.w, B2.w) - fmaxf(A.y, B2.y); iw = fmaxf(iw, 0.0f);
    float inter = ih * iw;
    return inter / (areaA + areaB - inter + 1e-8f);
}

// key pack: [score bits:32 | (16383-n):14 | slot:9]
__device__ __forceinline__ unsigned long long pack_key(float s, unsigned n,
                                                       unsigned slot) {
    return ((unsigned long long)__float_as_uint(s) << 32)
         | ((unsigned long long)((16383u - n) & 0x3FFFu) << 9)
         | (unsigned long long)(slot & 0x1FFu);
}

// Warp-register bitonic sort of 32 u64 keys, descending; no barriers.
__device__ __forceinline__ unsigned long long warpsort32_desc(
        unsigned long long key, int lane) {
#pragma unroll
    for (int k = 2; k <= 32; k <<= 1) {
#pragma unroll
        for (int j = k >> 1; j >= 1; j >>= 1) {
            unsigned long long other = __shfl_xor_sync(FULLM, key, j);
            bool dd   = ((lane & k) == 0);
            bool low  = ((lane & j) == 0);
            bool wmax = (dd == low);
            key = wmax ? (key > other ? key : other)
                       : (key < other ? key : other);
        }
    }
    return key;
}

// ---------------------------------------------------------------------------
// Kernel B: per-(b,c): streaming threshold-collect -> 16 warp-sorted runs ->
// single-warp 16-way merge-pop fused with greedy NMS.
// 256 threads (8 blocks/SM => 2x residency for the serial pop phase).
// ---------------------------------------------------------------------------
__global__ __launch_bounds__(256) void nms_kernel() {
    const int bc   = blockIdx.x;
    const int b    = bc / CC;
    const int c    = bc % CC;
    const int tid  = threadIdx.x;
    const int lane = tid & 31;
    const int wid  = tid >> 5;

    __shared__ unsigned long long sk[512];
    __shared__ float4             sbox[512];
    __shared__ int                hist[1024];     // fallback only
    __shared__ int                s_count, s_cut;

    if (tid == 0) s_count = 0;
    __syncthreads();

    const float4* S4 = (const float4*)(g_scoresT4 + ((size_t)b * CC + c) * NN4);
    const float   th = (c == 0) ? TH_0 : TH_C;

    // Single streaming pass: collect all scores >= th
    for (int i = tid; i < NN4; i += 256) {
        float4 v = S4[i];
        float ss[4] = { v.x, v.y, v.z, v.w };
#pragma unroll
        for (int k = 0; k < 4; k++) {
            float s = ss[k];
            if (s >= th) {
                int p = atomicAdd(&s_count, 1);
                if (p < 512) sk[p] = pack_key(s, (unsigned)(i * 4 + k),
                                              (unsigned)p);
            }
        }
    }
    __syncthreads();
    int cnt = s_count;

    if (cnt < KCAND || cnt > 512) {
        // Exact fallback (statistically never taken): histogram two-pass
        for (int i = tid; i < 1024; i += 256) hist[i] = 0;
        if (tid == 0) s_count = 0;
        __syncthreads();
        for (int i = tid; i < NN4; i += 256) {
            float4 v = S4[i];
            float ss[4] = { v.x, v.y, v.z, v.w };
#pragma unroll
            for (int k = 0; k < 4; k++) {
                float s = ss[k];
                if (s > 0.0f)
                    atomicAdd(&hist[min((int)(s * 1024.0f), 1023)], 1);
            }
        }
        __syncthreads();
        if (tid == 0) {
            int cum = 0, cut = 0;
            for (int bin = 1023; bin >= 0; bin--) {
                cum += hist[bin];
                if (cum >= KCAND) { cut = bin; break; }
            }
            s_cut = cut;
        }
        __syncthreads();
        const int fcut = s_cut;
        for (int i = tid; i < NN4; i += 256) {
            float4 v = S4[i];
            float ss[4] = { v.x, v.y, v.z, v.w };
#pragma unroll
            for (int k = 0; k < 4; k++) {
                float s = ss[k];
                if (s > 0.0f && min((int)(s * 1024.0f), 1023) >= fcut) {
                    int p = atomicAdd(&s_count, 1);
                    if (p < 512) sk[p] = pack_key(s, (unsigned)(i * 4 + k),
                                                  (unsigned)p);
                }
            }
        }
        __syncthreads();
        cnt = s_count;
    }

    const int mn = min(cnt, 512);
    for (int i = mn + tid; i < 512; i += 256) sk[i] = 0ULL;
    __syncthreads();

    // Prefetch boxes (slot-indexed) + 16 barrier-free warp sorts (2 per warp)
    unsigned long long k1 = sk[tid];
    unsigned long long k2 = sk[tid + 256];
    if (tid < mn) {
        unsigned n = 16383u - (unsigned)((k1 >> 9) & 0x3FFFu);
        sbox[tid] = g_boxes[(size_t)b * NN + n];
    }
    if (tid + 256 < mn) {
        unsigned n = 16383u - (unsigned)((k2 >> 9) & 0x3FFFu);
        sbox[tid + 256] = g_boxes[(size_t)b * NN + n];
    }
    k1 = warpsort32_desc(k1, lane);
    k2 = warpsort32_desc(k2, lane);
    sk[tid]       = k1;
    sk[tid + 256] = k2;
    __syncthreads();

    // Warp 0: 16-way merge-pop fused with greedy NMS (exact top-200 order)
    if (wid == 0) {
        const int outbase = bc * MAXPC;
        int    head   = 0;
        int    kc     = 0;
        int    pops   = 0;
        const int maxpops = min(mn, KCAND);
        float4 mykept = make_float4(0.f, 0.f, 0.f, 0.f);

        while (pops < maxpops && kc < MAXPC) {
            unsigned long long hk = 0ULL;
            if (lane < 16 && head < 32) hk = sk[lane * 32 + head];
            // butterfly argmax (keys unique; 0 = exhausted)
            unsigned long long bk = hk;
            int bl = lane;
#pragma unroll
            for (int off = 16; off >= 1; off >>= 1) {
                unsigned long long ok = __shfl_xor_sync(FULLM, bk, off);
                int                ol = __shfl_xor_sync(FULLM, bl, off);
                if (ok > bk) { bk = ok; bl = ol; }
            }
            if (bk == 0ULL) break;
            if (lane == bl) head++;
            pops++;

            float s = __uint_as_float((unsigned)(bk >> 32));
            if (s <= 0.5f) break;               // sorted: all later smaller
            int slot = (int)(bk & 0x1FFu);
            float4 cb = sbox[slot];             // smem broadcast

            bool ov = (lane < kc) && (iou_f(mykept, cb) > 0.5f);
            if (!__ballot_sync(FULLM, ov)) {
                if (lane == kc) mykept = cb;
                if (lane == 0) {
                    g_cls_scores[outbase + kc] = s;
                    g_cls_boxes[outbase + kc]  = cb;
                }
                kc++;
            }
        }
        if (lane < MAXPC && lane >= kc) {
            g_cls_scores[outbase + lane] = 0.0f;
            g_cls_boxes[outbase + lane]  = make_float4(0.f, 0.f, 0.f, 0.f);
        }
    }
}

// ---------------------------------------------------------------------------
// Kernel C: rank-based per-batch top-20 of 420 entries. One block per batch,
// 448 threads. rank(i) = #{keys > key_i}; ranks 0..19 write output directly.
// Fully parallel, no serial merge chain, no sort.
// ---------------------------------------------------------------------------
__global__ __launch_bounds__(448) void merge_kernel(float* __restrict__ out) {
    const int b   = blockIdx.x;
    const int tid = threadIdx.x;

    __shared__ unsigned long long ks[CC * MAXPC];   // 420 keys

    float s = 0.0f;
    if (tid < CC * MAXPC) {
        s = g_cls_scores[b * CC * MAXPC + tid];
        // key: [score bits:32 | (1023-flat):16]; > => (score desc, flat asc)
        ks[tid] = ((unsigned long long)__float_as_uint(s) << 16)
                  | (unsigned long long)(1023 - tid);
    }
    __syncthreads();

    if (tid < CC * MAXPC) {
        const unsigned long long myk = ks[tid];
        int rank = 0;
        // broadcast smem reads: every thread scans the same sequence
#pragma unroll 4
        for (int j = 0; j < CC * MAXPC; j++)
            rank += (ks[j] > myk);

        if (rank < MAXTOT) {
            float4 bx  = make_float4(0.f, 0.f, 0.f, 0.f);
            float  lab = 0.0f;
            if (s > 0.0f) {
                bx = g_cls_boxes[b * CC * MAXPC + tid];
                bx.x = fminf(fmaxf(bx.x, 0.0f), 1.0f);
                bx.y = fminf(fmaxf(bx.y, 0.0f), 1.0f);
                bx.z = fminf(fmaxf(bx.z, 0.0f), 1.0f);
                bx.w = fminf(fmaxf(bx.w, 0.0f), 1.0f);
                lab = (float)(tid / MAXPC);
            }
            // Output layout: boxes [B,20,4] | vals [B,20] | labels [B,20]
            float* ob = out + (size_t)b * MAXTOT * 4;
            float* ov = out + (size_t)BB * MAXTOT * 4 + (size_t)b * MAXTOT;
            float* ol = out + (size_t)BB * MAXTOT * 4 + (size_t)BB * MAXTOT
                            + (size_t)b * MAXTOT;
            ob[rank * 4 + 0] = bx.x;
            ob[rank * 4 + 1] = bx.y;
            ob[rank * 4 + 2] = bx.z;
            ob[rank * 4 + 3] = bx.w;
            ov[rank] = s;
            ol[rank] = lab;
        }
    }
}

// ---------------------------------------------------------------------------
extern "C" void kernel_launch(void* const* d_in, const int* in_sizes, int n_in,
                              void* d_out, int out_size) {
    const float* deltas  = (const float*)d_in[0];  // (64, 8732, 4)
    const float* labels  = (const float*)d_in[1];  // (64, 8732, 21)
    const float* anchors = (const float*)d_in[2];  // (8732, 4)
    float* out = (float*)d_out;

    decode_kernel<<<BB * NTILES, TILE>>>(deltas, labels, anchors);
    nms_kernel<<<BB * CC, 256>>>();
    merge_kernel<<<BB, 448>>>(out);
}

// round 12
// speedup vs baseline: 1.6957x; 1.2497x over previous
#include <cuda_runtime.h>
#include <math.h>

// Problem constants
#define BB 64
#define NN 8732
#define CC 21
#define KCAND 200
#define MAXPC 20
#define MAXTOT 20
#define FULLM 0xffffffffu

#define TH_C  0.96f             // collect threshold, classes >= 1 (proven R9/R11)
#define TH_0  0.92f             // collect threshold, class 0      (proven R9/R11)

#define TILE 128
#define NTILES ((NN + TILE - 1) / TILE)   // 69
#define SLP 129                           // padded smem pitch
#define NWORDS (NTILES * 4)               // 276 mask words per (b,c)

// Scratch (static device globals: allowed; no runtime allocation)
__device__ float4        g_boxes[BB * NN];                 // decoded boxes
__device__ unsigned char g_mask[BB * NN];                  // argmax != 0 (fallback)
__device__ unsigned      g_cmask[(size_t)BB * CC * NWORDS];// candidate bitmask
__device__ float         g_cls_scores[BB * CC * MAXPC];    // sorted desc
__device__ float4        g_cls_boxes[BB * CC * MAXPC];

// ---------------------------------------------------------------------------
// Kernel A: decode + argmax mask + candidate BITMASK write (1.5MB instead of
// the 47MB transposed score tensor). Tile structure identical to the
// measured-24us version; only the final write phase changes.
// ---------------------------------------------------------------------------
__global__ __launch_bounds__(TILE) void decode_kernel(
        const float* __restrict__ deltas,
        const float* __restrict__ labels,
        const float* __restrict__ anchors) {
    const int b    = blockIdx.x / NTILES;
    const int tile = blockIdx.x % NTILES;
    const int n0   = tile * TILE;
    const int cnt  = min(TILE, NN - n0);
    const int t    = threadIdx.x;
    const int lane = t & 31;
    const int warp = t >> 5;

    __shared__ float sl[CC * SLP];

    const float* Lb  = labels + ((size_t)b * NN + n0) * CC;
    const int    tot = cnt * CC;
    for (int idx = t; idx < tot; idx += TILE) {
        int i = idx / CC;
        int c = idx - i * CC;
        sl[c * SLP + i] = Lb[idx];
    }
    __syncthreads();

    bool masked = false;
    if (t < cnt) {
        // argmax over 21 classes (first-occurrence ties, like jnp.argmax)
        float best = sl[t];
        int   bi   = 0;
#pragma unroll
        for (int c = 1; c < CC; c++) {
            float v = sl[c * SLP + t];
            if (v > best) { best = v; bi = c; }
        }
        masked = (bi != 0);
        const int n = n0 + t;
        g_mask[(size_t)b * NN + n] = masked ? 1 : 0;

        // decode box
        float4 a = __ldg(((const float4*)anchors) + n);
        float4 d = __ldg(((const float4*)deltas) + (size_t)b * NN + n);
        d.x *= 0.1f; d.y *= 0.1f; d.z *= 0.2f; d.w *= 0.2f;

        float ah  = a.z - a.x;
        float aw  = a.w - a.y;
        float acy = a.x + 0.5f * ah;
        float acx = a.y + 0.5f * aw;
        float cy  = d.x * ah + acy;
        float cx  = d.y * aw + acx;
        float h   = expf(d.z) * ah;
        float w   = expf(d.w) * aw;

        g_boxes[(size_t)b * NN + n] = make_float4(cy - 0.5f * h, cx - 0.5f * w,
                                                  cy + 0.5f * h, cx + 0.5f * w);
    }

    // Candidate bitmask: one ballot per (class, warp); bit set iff this
    // anchor's masked score >= per-class threshold.
#pragma unroll
    for (int c = 0; c < CC; c++) {
        const float th = (c == 0) ? TH_0 : TH_C;
        bool pred = (t < cnt) && masked && (sl[c * SLP + t] >= th);
        unsigned bal = __ballot_sync(FULLM, pred);
        if (lane == 0)
            g_cmask[((size_t)(b * CC + c) * NTILES + tile) * 4 + warp] = bal;
    }
}

// ---------------------------------------------------------------------------
// IoU, exactly mirroring the reference fp32 formula
// ---------------------------------------------------------------------------
__device__ __forceinline__ float iou_f(float4 A, float4 B2) {
    float areaA = (A.z - A.x) * (A.w - A.y);
    float areaB = (B2.z - B2.x) * (B2.w - B2.y);
    float ih = fminf(A.z, B2.z) - fmaxf(A.x, B2.x); ih = fmaxf(ih, 0.0f);
    float iw = fminf(A.w, B2.w) - fmaxf(A.y, B2.y); iw = fmaxf(iw, 0.0f);
    float inter = ih * iw;
    return inter / (areaA + areaB - inter + 1e-8f);
}

// key pack: [score bits:32 | (16383-n):14 | slot:9]
__device__ __forceinline__ unsigned long long pack_key(float s, unsigned n,
                                                       unsigned slot) {
    return ((unsigned long long)__float_as_uint(s) << 32)
         | ((unsigned long long)((16383u - n) & 0x3FFFu) << 9)
         | (unsigned long long)(slot & 0x1FFu);
}

// Warp-register bitonic sort of 32 u64 keys, descending; no barriers.
__device__ __forceinline__ unsigned long long warpsort32_desc(
        unsigned long long key, int lane) {
#pragma unroll
    for (int k = 2; k <= 32; k <<= 1) {
#pragma unroll
        for (int j = k >> 1; j >= 1; j >>= 1) {
            unsigned long long other = __shfl_xor_sync(FULLM, key, j);
            bool dd   = ((lane & k) == 0);
            bool low  = ((lane & j) == 0);
            bool wmax = (dd == low);
            key = wmax ? (key > other ? key : other)
                       : (key < other ? key : other);
        }
    }
    return key;
}

// ---------------------------------------------------------------------------
// Kernel B: per-(b,c): read 1.1KB bitmask -> gather ~350 scores/boxes ->
// 16 warp-sorted runs -> single-warp merge-pop fused with greedy NMS.
// ---------------------------------------------------------------------------
__global__ __launch_bounds__(256) void nms_kernel(const float* __restrict__ labels) {
    const int bc   = blockIdx.x;
    const int b    = bc / CC;
    const int c    = bc % CC;
    const int tid  = threadIdx.x;
    const int lane = tid & 31;
    const int wid  = tid >> 5;

    __shared__ unsigned long long sk[512];
    __shared__ float4             sbox[512];
    __shared__ int                hist[1024];     // fallback only
    __shared__ int                s_count, s_cut;

    if (tid == 0) s_count = 0;
    __syncthreads();

    // Extract candidates from the bitmask; gather scores from labels.
    const unsigned* Cm = g_cmask + (size_t)bc * NWORDS;
    for (int widx = tid; widx < NWORDS; widx += 256) {
        unsigned m = Cm[widx];
        while (m) {
            int bit = __ffs(m) - 1;
            m &= m - 1;
            int n = (widx >> 2) * TILE + (widx & 3) * 32 + bit;
            float s = __ldg(labels + ((size_t)b * NN + n) * CC + c);
            int p = atomicAdd(&s_count, 1);
            if (p < 512) sk[p] = pack_key(s, (unsigned)n, (unsigned)p);
        }
    }
    __syncthreads();
    int cnt = s_count;

    if (cnt < KCAND || cnt > 512) {
        // Exact fallback (statistically never taken): histogram two-pass on
        // raw labels (strided) + argmax mask.
        for (int i = tid; i < 1024; i += 256) hist[i] = 0;
        if (tid == 0) s_count = 0;
        __syncthreads();

        const float*         Lcol = labels + (size_t)b * NN * CC + c;
        const unsigned char* Mb   = g_mask + (size_t)b * NN;

        for (int n = tid; n < NN; n += 256) {
            if (Mb[n]) {
                float s = Lcol[(size_t)n * CC];
                if (s > 0.0f)
                    atomicAdd(&hist[min((int)(s * 1024.0f), 1023)], 1);
            }
        }
        __syncthreads();
        if (tid == 0) {
            int cum = 0, cut = 0;
            for (int bin = 1023; bin >= 0; bin--) {
                cum += hist[bin];
                if (cum >= KCAND) { cut = bin; break; }
            }
            s_cut = cut;
        }
        __syncthreads();
        const int fcut = s_cut;
        for (int n = tid; n < NN; n += 256) {
            if (Mb[n]) {
                float s = Lcol[(size_t)n * CC];
                if (s > 0.0f && min((int)(s * 1024.0f), 1023) >= fcut) {
                    int p = atomicAdd(&s_count, 1);
                    if (p < 512)
                        sk[p] = pack_key(s, (unsigned)n, (unsigned)p);
                }
            }
        }
        __syncthreads();
        cnt = s_count;
    }

    const int mn = min(cnt, 512);
    for (int i = mn + tid; i < 512; i += 256) sk[i] = 0ULL;
    __syncthreads();

    // Prefetch boxes (slot-indexed) + 16 barrier-free warp sorts (2 per warp)
    unsigned long long k1 = sk[tid];
    unsigned long long k2 = sk[tid + 256];
    if (tid < mn) {
        unsigned n = 16383u - (unsigned)((k1 >> 9) & 0x3FFFu);
        sbox[tid] = g_boxes[(size_t)b * NN + n];
    }
    if (tid + 256 < mn) {
        unsigned n = 16383u - (unsigned)((k2 >> 9) & 0x3FFFu);
        sbox[tid + 256] = g_boxes[(size_t)b * NN + n];
    }
    k1 = warpsort32_desc(k1, lane);
    k2 = warpsort32_desc(k2, lane);
    sk[tid]       = k1;
    sk[tid + 256] = k2;
    __syncthreads();

    // Warp 0: 16-way merge-pop fused with greedy NMS (exact top-200 order)
    if (wid == 0) {
        const int outbase = bc * MAXPC;
        int    head   = 0;
        int    kc     = 0;
        int    pops   = 0;
        const int maxpops = min(mn, KCAND);
        float4 mykept = make_float4(0.f, 0.f, 0.f, 0.f);

        while (pops < maxpops && kc < MAXPC) {
            unsigned long long hk = 0ULL;
            if (lane < 16 && head < 32) hk = sk[lane * 32 + head];
            // butterfly argmax (keys unique; 0 = exhausted)
            unsigned long long bk = hk;
            int bl = lane;
#pragma unroll
            for (int off = 16; off >= 1; off >>= 1) {
                unsigned long long ok = __shfl_xor_sync(FULLM, bk, off);
                int                ol = __shfl_xor_sync(FULLM, bl, off);
                if (ok > bk) { bk = ok; bl = ol; }
            }
            if (bk == 0ULL) break;
            if (lane == bl) head++;
            pops++;

            float s = __uint_as_float((unsigned)(bk >> 32));
            if (s <= 0.5f) break;               // sorted: all later smaller
            int slot = (int)(bk & 0x1FFu);
            float4 cb = sbox[slot];             // smem broadcast

            bool ov = (lane < kc) && (iou_f(mykept, cb) > 0.5f);
            if (!__ballot_sync(FULLM, ov)) {
                if (lane == kc) mykept = cb;
                if (lane == 0) {
                    g_cls_scores[outbase + kc] = s;
                    g_cls_boxes[outbase + kc]  = cb;
                }
                kc++;
            }
        }
        if (lane < MAXPC && lane >= kc) {
            g_cls_scores[outbase + lane] = 0.0f;
            g_cls_boxes[outbase + lane]  = make_float4(0.f, 0.f, 0.f, 0.f);
        }
    }
}

// ---------------------------------------------------------------------------
// Kernel C (R11-measured ~3us): rank-based per-batch top-20 of 420 entries.
// ---------------------------------------------------------------------------
__global__ __launch_bounds__(448) void merge_kernel(float* __restrict__ out) {
    const int b   = blockIdx.x;
    const int tid = threadIdx.x;

    __shared__ unsigned long long ks[CC * MAXPC];   // 420 keys

    float s = 0.0f;
    if (tid < CC * MAXPC) {
        s = g_cls_scores[b * CC * MAXPC + tid];
        // key: [score bits:32 | (1023-flat):16]; > => (score desc, flat asc)
        ks[tid] = ((unsigned long long)__float_as_uint(s) << 16)
                  | (unsigned long long)(1023 - tid);
    }
    __syncthreads();

    if (tid < CC * MAXPC) {
        const unsigned long long myk = ks[tid];
        int rank = 0;
#pragma unroll 4
        for (int j = 0; j < CC * MAXPC; j++)
            rank += (ks[j] > myk);

        if (rank < MAXTOT) {
            float4 bx  = make_float4(0.f, 0.f, 0.f, 0.f);
            float  lab = 0.0f;
            if (s > 0.0f) {
                bx = g_cls_boxes[b * CC * MAXPC + tid];
                bx.x = fminf(fmaxf(bx.x, 0.0f), 1.0f);
                bx.y = fminf(fmaxf(bx.y, 0.0f), 1.0f);
                bx.z = fminf(fmaxf(bx.z, 0.0f), 1.0f);
                bx.w = fminf(fmaxf(bx.w, 0.0f), 1.0f);
                lab = (float)(tid / MAXPC);
            }
            // Output layout: boxes [B,20,4] | vals [B,20] | labels [B,20]
            float* ob = out + (size_t)b * MAXTOT * 4;
            float* ov = out + (size_t)BB * MAXTOT * 4 + (size_t)b * MAXTOT;
            float* ol = out + (size_t)BB * MAXTOT * 4 + (size_t)BB * MAXTOT
                            + (size_t)b * MAXTOT;
            ob[rank * 4 + 0] = bx.x;
            ob[rank * 4 + 1] = bx.y;
            ob[rank * 4 + 2] = bx.z;
            ob[rank * 4 + 3] = bx.w;
            ov[rank] = s;
            ol[rank] = lab;
        }
    }
}

// ---------------------------------------------------------------------------
extern "C" void kernel_launch(void* const* d_in, const int* in_sizes, int n_in,
                              void* d_out, int out_size) {
    const float* deltas  = (const float*)d_in[0];  // (64, 8732, 4)
    const float* labels  = (const float*)d_in[1];  // (64, 8732, 21)
    const float* anchors = (const float*)d_in[2];  // (8732, 4)
    float* out = (float*)d_out;

    decode_kernel<<<BB * NTILES, TILE>>>(deltas, labels, anchors);
    nms_kernel<<<BB * CC, 256>>>(labels);
    merge_kernel<<<BB, 448>>>(out);
}

// round 13
// speedup vs baseline: 1.8898x; 1.1145x over previous
#include <cuda_runtime.h>
#include <math.h>

// Problem constants
#define BB 64
#define NN 8732
#define CC 21
#define KCAND 200
#define MAXPC 20
#define MAXTOT 20
#define FULLM 0xffffffffu

#define TH_C  0.96f             // collect threshold, classes >= 1 (proven)
#define TH_0  0.92f             // collect threshold, class 0      (proven)

#define DB  256                           // decode block size
#define BPB ((NN + DB - 1) / DB)          // 35 decode blocks per batch
#define NW  ((NN + 31) / 32)              // 273 mask words per (b,c)

// Scratch (static device globals: allowed; no runtime allocation)
__device__ float4        g_boxes[BB * NN];                 // decoded boxes
__device__ unsigned char g_mask[BB * NN];                  // argmax != 0 (fallback)
__device__ unsigned      g_cmask[(size_t)BB * CC * NW];    // candidate bitmask
__device__ float         g_cls_scores[BB * CC * MAXPC];    // sorted desc
__device__ float4        g_cls_boxes[BB * CC * MAXPC];

// ---------------------------------------------------------------------------
// Kernel A: one thread per (b,n); scores in registers; barrier-free.
// Emits decoded box, argmax mask byte, and 21 candidate ballots per warp.
// ---------------------------------------------------------------------------
__global__ __launch_bounds__(DB) void decode_kernel(
        const float* __restrict__ deltas,
        const float* __restrict__ labels,
        const float* __restrict__ anchors) {
    const int bx   = blockIdx.x;
    const int b    = bx / BPB;
    const int blk  = bx % BPB;
    const int n    = blk * DB + threadIdx.x;
    const int lane = threadIdx.x & 31;
    const bool valid = (n < NN);

    float sc[CC];
    bool  masked = false;

    if (valid) {
        const float* lr = labels + ((size_t)b * NN + n) * CC;
#pragma unroll
        for (int c = 0; c < CC; c++) sc[c] = __ldg(lr + c);

        // argmax (first-occurrence ties, like jnp.argmax)
        float best = sc[0];
        int   bi   = 0;
#pragma unroll
        for (int c = 1; c < CC; c++) {
            if (sc[c] > best) { best = sc[c]; bi = c; }
        }
        masked = (bi != 0);
        g_mask[(size_t)b * NN + n] = masked ? 1 : 0;

        // decode box
        float4 a = __ldg(((const float4*)anchors) + n);
        float4 d = __ldg(((const float4*)deltas) + (size_t)b * NN + n);
        d.x *= 0.1f; d.y *= 0.1f; d.z *= 0.2f; d.w *= 0.2f;

        float ah  = a.z - a.x;
        float aw  = a.w - a.y;
        float acy = a.x + 0.5f * ah;
        float acx = a.y + 0.5f * aw;
        float cy  = d.x * ah + acy;
        float cx  = d.y * aw + acx;
        float h   = expf(d.z) * ah;
        float w   = expf(d.w) * aw;

        g_boxes[(size_t)b * NN + n] = make_float4(cy - 0.5f * h, cx - 0.5f * w,
                                                  cy + 0.5f * h, cx + 0.5f * w);
    }

    // Candidate ballots: word index = n>>5; skip warps fully past NN.
    const int  w      = n >> 5;
    const bool wvalid = (blk * DB + (threadIdx.x & ~31)) < NN;
#pragma unroll
    for (int c = 0; c < CC; c++) {
        const float th  = (c == 0) ? TH_0 : TH_C;
        bool pred = valid && masked && (sc[c] >= th);
        unsigned bal = __ballot_sync(FULLM, pred);
        if (lane == 0 && wvalid)
            g_cmask[(size_t)(b * CC + c) * NW + w] = bal;
    }
}

// ---------------------------------------------------------------------------
// IoU, exactly mirroring the reference fp32 formula
// ---------------------------------------------------------------------------
__device__ __forceinline__ float iou_f(float4 A, float4 B2) {
    float areaA = (A.z - A.x) * (A.w - A.y);
    float areaB = (B2.z - B2.x) * (B2.w - B2.y);
    float ih = fminf(A.z, B2.z) - fmaxf(A.x, B2.x); ih = fmaxf(ih, 0.0f);
    float iw = fminf(A.w, B2.w) - fmaxf(A.y, B2.y); iw = fmaxf(iw, 0.0f);
    float inter = ih * iw;
    return inter / (areaA + areaB - inter + 1e-8f);
}

// key pack: [score bits:32 | (16383-n):14 | slot:9]
__device__ __forceinline__ unsigned long long pack_key(float s, unsigned n,
                                                       unsigned slot) {
    return ((unsigned long long)__float_as_uint(s) << 32)
         | ((unsigned long long)((16383u - n) & 0x3FFFu) << 9)
         | (unsigned long long)(slot & 0x1FFu);
}

// Warp-register bitonic sort of 32 u64 keys, descending; no barriers.
__device__ __forceinline__ unsigned long long warpsort32_desc(
        unsigned long long key, int lane) {
#pragma unroll
    for (int k = 2; k <= 32; k <<= 1) {
#pragma unroll
        for (int j = k >> 1; j >= 1; j >>= 1) {
            unsigned long long other = __shfl_xor_sync(FULLM, key, j);
            bool dd   = ((lane & k) == 0);
            bool low  = ((lane & j) == 0);
            bool wmax = (dd == low);
            key = wmax ? (key > other ? key : other)
                       : (key < other ? key : other);
        }
    }
    return key;
}

// ---------------------------------------------------------------------------
// Kernel B: per-(b,c): scan-based bitmask collect (no atomics) -> gather
// scores/boxes -> 16 warp-sorted runs -> single-warp merge-pop greedy NMS.
// 128 threads, min 10 blocks/SM => all 1344 blocks resident in ONE wave.
// ---------------------------------------------------------------------------
__global__ __launch_bounds__(128, 10) void nms_kernel(
        const float* __restrict__ labels) {
    const int bc   = blockIdx.x;
    const int b    = bc / CC;
    const int c    = bc % CC;
    const int tid  = threadIdx.x;
    const int lane = tid & 31;
    const int wid  = tid >> 5;

    __shared__ unsigned long long sk[512];
    __shared__ float4             sbox[512];      // fallback hist aliases this
    __shared__ int                swarp[4];
    __shared__ int                s_count, s_cut;
    int* hist = (int*)sbox;                       // 1024 ints = 4KB <= 8KB

    // ---- Scan-based collect from bitmask (deterministic slots, no atomics)
    const unsigned* Cm = g_cmask + (size_t)bc * NW;
    unsigned mw[3];
    int cnt_t = 0;
#pragma unroll
    for (int j = 0; j < 3; j++) {
        int widx = tid * 3 + j;
        mw[j] = (widx < NW) ? Cm[widx] : 0u;
        cnt_t += __popc(mw[j]);
    }
    // warp inclusive scan
    int inc = cnt_t;
#pragma unroll
    for (int off = 1; off < 32; off <<= 1) {
        int v = __shfl_up_sync(FULLM, inc, off);
        if (lane >= off) inc += v;
    }
    if (lane == 31) swarp[wid] = inc;
    __syncthreads();
    int wbase = 0;
#pragma unroll
    for (int k = 0; k < 4; k++) wbase += (k < wid) ? swarp[k] : 0;
    const int total = swarp[0] + swarp[1] + swarp[2] + swarp[3];
    int slot = wbase + inc - cnt_t;               // exclusive prefix

    int cnt = total;
    if (cnt >= KCAND && cnt <= 512) {
        // Fast path: extract bits, gather scores, write keys at scan slots
#pragma unroll
        for (int j = 0; j < 3; j++) {
            unsigned m = mw[j];
            const int nb = (tid * 3 + j) * 32;
            while (m) {
                int bit = __ffs(m) - 1;
                m &= m - 1;
                int n = nb + bit;
                float s = __ldg(labels + ((size_t)b * NN + n) * CC + c);
                sk[slot] = pack_key(s, (unsigned)n, (unsigned)slot);
                slot++;
            }
        }
    } else {
        // Exact fallback (statistically never taken): histogram two-pass
        for (int i = tid; i < 1024; i += 128) hist[i] = 0;
        if (tid == 0) s_count = 0;
        __syncthreads();

        const float*         Lcol = labels + (size_t)b * NN * CC + c;
        const unsigned char* Mb   = g_mask + (size_t)b * NN;

        for (int n = tid; n < NN; n += 128) {
            if (Mb[n]) {
                float s = Lcol[(size_t)n * CC];
                if (s > 0.0f)
                    atomicAdd(&hist[min((int)(s * 1024.0f), 1023)], 1);
            }
        }
        __syncthreads();
        if (tid == 0) {
            int cum = 0, cut = 0;
            for (int bin = 1023; bin >= 0; bin--) {
                cum += hist[bin];
                if (cum >= KCAND) { cut = bin; break; }
            }
            s_cut = cut;
        }
        __syncthreads();
        const int fcut = s_cut;
        for (int n = tid; n < NN; n += 128) {
            if (Mb[n]) {
                float s = Lcol[(size_t)n * CC];
                if (s > 0.0f && min((int)(s * 1024.0f), 1023) >= fcut) {
                    int p = atomicAdd(&s_count, 1);
                    if (p < 512)
                        sk[p] = pack_key(s, (unsigned)n, (unsigned)p);
                }
            }
        }
        __syncthreads();
        cnt = s_count;
    }
    __syncthreads();

    const int mn = min(cnt, 512);
    for (int i = mn + tid; i < 512; i += 128) sk[i] = 0ULL;
    __syncthreads();

    // Prefetch boxes (slot-indexed; slot == pre-sort position)
    for (int i = tid; i < 512; i += 128) {
        if (i < mn) {
            unsigned n = 16383u - (unsigned)((sk[i] >> 9) & 0x3FFFu);
            sbox[i] = g_boxes[(size_t)b * NN + n];
        }
    }
    // 16 barrier-free warp sorts (4 runs per warp)
#pragma unroll
    for (int r = 0; r < 4; r++) {
        const int run = wid * 4 + r;
        unsigned long long k = sk[run * 32 + lane];
        k = warpsort32_desc(k, lane);
        sk[run * 32 + lane] = k;
    }
    __syncthreads();

    // Warp 0: 16-way merge-pop fused with greedy NMS (exact top-200 order)
    if (wid == 0) {
        const int outbase = bc * MAXPC;
        int    head   = 0;
        int    kc     = 0;
        int    pops   = 0;
        const int maxpops = min(mn, KCAND);
        float4 mykept = make_float4(0.f, 0.f, 0.f, 0.f);

        while (pops < maxpops && kc < MAXPC) {
            unsigned long long hk = 0ULL;
            if (lane < 16 && head < 32) hk = sk[lane * 32 + head];
            // butterfly argmax (keys unique; 0 = exhausted)
            unsigned long long bk = hk;
            int bl = lane;
#pragma unroll
            for (int off = 16; off >= 1; off >>= 1) {
                unsigned long long ok = __shfl_xor_sync(FULLM, bk, off);
                int                ol = __shfl_xor_sync(FULLM, bl, off);
                if (ok > bk) { bk = ok; bl = ol; }
            }
            if (bk == 0ULL) break;
            if (lane == bl) head++;
            pops++;

            float s = __uint_as_float((unsigned)(bk >> 32));
            if (s <= 0.5f) break;               // sorted: all later smaller
            int sl2 = (int)(bk & 0x1FFu);
            float4 cb = sbox[sl2];              // smem broadcast

            bool ov = (lane < kc) && (iou_f(mykept, cb) > 0.5f);
            if (!__ballot_sync(FULLM, ov)) {
                if (lane == kc) mykept = cb;
                if (lane == 0) {
                    g_cls_scores[outbase + kc] = s;
                    g_cls_boxes[outbase + kc]  = cb;
                }
                kc++;
            }
        }
        if (lane < MAXPC && lane >= kc) {
            g_cls_scores[outbase + lane] = 0.0f;
            g_cls_boxes[outbase + lane]  = make_float4(0.f, 0.f, 0.f, 0.f);
        }
    }
}

// ---------------------------------------------------------------------------
// Kernel C (measured ~3us): rank-based per-batch top-20 of 420 entries.
// ---------------------------------------------------------------------------
__global__ __launch_bounds__(448) void merge_kernel(float* __restrict__ out) {
    const int b   = blockIdx.x;
    const int tid = threadIdx.x;

    __shared__ unsigned long long ks[CC * MAXPC];   // 420 keys

    float s = 0.0f;
    if (tid < CC * MAXPC) {
        s = g_cls_scores[b * CC * MAXPC + tid];
        // key: [score bits:32 | (1023-flat):16]; > => (score desc, flat asc)
        ks[tid] = ((unsigned long long)__float_as_uint(s) << 16)
                  | (unsigned long long)(1023 - tid);
    }
    __syncthreads();

    if (tid < CC * MAXPC) {
        const unsigned long long myk = ks[tid];
        int rank = 0;
#pragma unroll 4
        for (int j = 0; j < CC * MAXPC; j++)
            rank += (ks[j] > myk);

        if (rank < MAXTOT) {
            float4 bx  = make_float4(0.f, 0.f, 0.f, 0.f);
            float  lab = 0.0f;
            if (s > 0.0f) {
                bx = g_cls_boxes[b * CC * MAXPC + tid];
                bx.x = fminf(fmaxf(bx.x, 0.0f), 1.0f);
                bx.y = fminf(fmaxf(bx.y, 0.0f), 1.0f);
                bx.z = fminf(fmaxf(bx.z, 0.0f), 1.0f);
                bx.w = fminf(fmaxf(bx.w, 0.0f), 1.0f);
                lab = (float)(tid / MAXPC);
            }
            // Output layout: boxes [B,20,4] | vals [B,20] | labels [B,20]
            float* ob = out + (size_t)b * MAXTOT * 4;
            float* ov = out + (size_t)BB * MAXTOT * 4 + (size_t)b * MAXTOT;
            float* ol = out + (size_t)BB * MAXTOT * 4 + (size_t)BB * MAXTOT
                            + (size_t)b * MAXTOT;
            ob[rank * 4 + 0] = bx.x;
            ob[rank * 4 + 1] = bx.y;
            ob[rank * 4 + 2] = bx.z;
            ob[rank * 4 + 3] = bx.w;
            ov[rank] = s;
            ol[rank] = lab;
        }
    }
}

// ---------------------------------------------------------------------------
extern "C" void kernel_launch(void* const* d_in, const int* in_sizes, int n_in,
                              void* d_out, int out_size) {
    const float* deltas  = (const float*)d_in[0];  // (64, 8732, 4)
    const float* labels  = (const float*)d_in[1];  // (64, 8732, 21)
    const float* anchors = (const float*)d_in[2];  // (8732, 4)
    float* out = (float*)d_out;

    decode_kernel<<<BB * BPB, DB>>>(deltas, labels, anchors);
    nms_kernel<<<BB * CC, 128>>>(labels);
    merge_kernel<<<BB, 448>>>(out);
}

// round 14
// speedup vs baseline: 2.1096x; 1.1163x over previous
#include <cuda_runtime.h>
#include <math.h>

// Problem constants
#define BB 64
#define NN 8732
#define CC 21
#define KCAND 200
#define MAXPC 20
#define MAXTOT 20
#define FULLM 0xffffffffu

#define TH_C  0.96f             // collect threshold, classes >= 1 (proven)
#define TH_0  0.92f             // collect threshold, class 0      (proven)

#define DB  256                           // decode block size
#define BPB ((NN + DB - 1) / DB)          // 35 decode blocks per batch
#define NW  ((NN + 31) / 32)              // 273 mask words per (b,c)
#define PD  8                             // prefetched boxes per sorted run

// Scratch (static device globals: allowed; no runtime allocation)
__device__ float4        g_boxes[BB * NN];                 // decoded boxes
__device__ unsigned char g_mask[BB * NN];                  // argmax != 0 (fallback)
__device__ unsigned      g_cmask[(size_t)BB * CC * NW];    // candidate bitmask
__device__ float         g_cls_scores[BB * CC * MAXPC];    // sorted desc
__device__ float4        g_cls_boxes[BB * CC * MAXPC];

// ---------------------------------------------------------------------------
// Kernel A (measured 16.3us, unchanged): one thread per (b,n); registers;
// emits decoded box, argmax mask byte, 21 candidate ballots per warp.
// ---------------------------------------------------------------------------
__global__ __launch_bounds__(DB) void decode_kernel(
        const float* __restrict__ deltas,
        const float* __restrict__ labels,
        const float* __restrict__ anchors) {
    const int bx   = blockIdx.x;
    const int b    = bx / BPB;
    const int blk  = bx % BPB;
    const int n    = blk * DB + threadIdx.x;
    const int lane = threadIdx.x & 31;
    const bool valid = (n < NN);

    float sc[CC];
    bool  masked = false;

    if (valid) {
        const float* lr = labels + ((size_t)b * NN + n) * CC;
#pragma unroll
        for (int c = 0; c < CC; c++) sc[c] = __ldg(lr + c);

        float best = sc[0];
        int   bi   = 0;
#pragma unroll
        for (int c = 1; c < CC; c++) {
            if (sc[c] > best) { best = sc[c]; bi = c; }
        }
        masked = (bi != 0);
        g_mask[(size_t)b * NN + n] = masked ? 1 : 0;

        float4 a = __ldg(((const float4*)anchors) + n);
        float4 d = __ldg(((const float4*)deltas) + (size_t)b * NN + n);
        d.x *= 0.1f; d.y *= 0.1f; d.z *= 0.2f; d.w *= 0.2f;

        float ah  = a.z - a.x;
        float aw  = a.w - a.y;
        float acy = a.x + 0.5f * ah;
        float acx = a.y + 0.5f * aw;
        float cy  = d.x * ah + acy;
        float cx  = d.y * aw + acx;
        float h   = expf(d.z) * ah;
        float w   = expf(d.w) * aw;

        g_boxes[(size_t)b * NN + n] = make_float4(cy - 0.5f * h, cx - 0.5f * w,
                                                  cy + 0.5f * h, cx + 0.5f * w);
    }

    const int  w      = n >> 5;
    const bool wvalid = (blk * DB + (threadIdx.x & ~31)) < NN;
#pragma unroll
    for (int c = 0; c < CC; c++) {
        const float th  = (c == 0) ? TH_0 : TH_C;
        bool pred = valid && masked && (sc[c] >= th);
        unsigned bal = __ballot_sync(FULLM, pred);
        if (lane == 0 && wvalid)
            g_cmask[(size_t)(b * CC + c) * NW + w] = bal;
    }
}

// ---------------------------------------------------------------------------
// IoU, exactly mirroring the reference fp32 formula
// ---------------------------------------------------------------------------
__device__ __forceinline__ float iou_f(float4 A, float4 B2) {
    float areaA = (A.z - A.x) * (A.w - A.y);
    float areaB = (B2.z - B2.x) * (B2.w - B2.y);
    float ih = fminf(A.z, B2.z) - fmaxf(A.x, B2.x); ih = fmaxf(ih, 0.0f);
    float iw = fminf(A.w, B2.w) - fmaxf(A.y, B2.y); iw = fmaxf(iw, 0.0f);
    float inter = ih * iw;
    return inter / (areaA + areaB - inter + 1e-8f);
}

// key pack: [score bits:32 | (16383-n):14 | 0:9] — desc => score desc, n asc
__device__ __forceinline__ unsigned long long pack_key(float s, unsigned n) {
    return ((unsigned long long)__float_as_uint(s) << 32)
         | ((unsigned long long)((16383u - n) & 0x3FFFu) << 9);
}

// Warp-register bitonic sort of 32 u64 keys, descending; no barriers.
__device__ __forceinline__ unsigned long long warpsort32_desc(
        unsigned long long key, int lane) {
#pragma unroll
    for (int k = 2; k <= 32; k <<= 1) {
#pragma unroll
        for (int j = k >> 1; j >= 1; j >>= 1) {
            unsigned long long other = __shfl_xor_sync(FULLM, key, j);
            bool dd   = ((lane & k) == 0);
            bool low  = ((lane & j) == 0);
            bool wmax = (dd == low);
            key = wmax ? (key > other ? key : other)
                       : (key < other ? key : other);
        }
    }
    return key;
}

// ---------------------------------------------------------------------------
// Kernel B: per-(b,c): scan collect (MLP-batched gather) -> warp-sorted runs
// (active runs only) -> lazy top-PD box prefetch -> redux-based merge-pop NMS.
// ---------------------------------------------------------------------------
__global__ __launch_bounds__(128, 10) void nms_kernel(
        const float* __restrict__ labels) {
    const int bc   = blockIdx.x;
    const int b    = bc / CC;
    const int c    = bc % CC;
    const int tid  = threadIdx.x;
    const int lane = tid & 31;
    const int wid  = tid >> 5;

    __shared__ unsigned long long sk[512];        // fallback hist aliases this
    __shared__ float4             sbox[16 * PD];  // prefetched boxes per run
    __shared__ int                swarp[4];
    __shared__ int                s_count, s_cut;
    int* hist = (int*)sk;                         // 1024 ints = 4KB

    // ---- Scan-based collect from bitmask (no atomics)
    const unsigned* Cm = g_cmask + (size_t)bc * NW;
    unsigned mw[3];
    int cnt_t = 0;
#pragma unroll
    for (int j = 0; j < 3; j++) {
        int widx = tid * 3 + j;
        mw[j] = (widx < NW) ? Cm[widx] : 0u;
        cnt_t += __popc(mw[j]);
    }
    int inc = cnt_t;
#pragma unroll
    for (int off = 1; off < 32; off <<= 1) {
        int v = __shfl_up_sync(FULLM, inc, off);
        if (lane >= off) inc += v;
    }
    if (lane == 31) swarp[wid] = inc;
    __syncthreads();
    int wbase = 0;
#pragma unroll
    for (int k = 0; k < 4; k++) wbase += (k < wid) ? swarp[k] : 0;
    const int total    = swarp[0] + swarp[1] + swarp[2] + swarp[3];
    const int slotbase = wbase + inc - cnt_t;     // exclusive prefix

    int cnt = total;
    if (cnt >= KCAND && cnt <= 512) {
        // Fast path: extract bit positions (ALU), then batched independent
        // loads (MLP up to 12), then packed key stores.
        int myn[12];
        int idx = 0;
#pragma unroll
        for (int j = 0; j < 3; j++) {
            unsigned m = mw[j];
            const int nb = (tid * 3 + j) * 32;
            while (m) {
                int bit = __ffs(m) - 1;
                m &= m - 1;
                int n = nb + bit;
                if (idx < 12) {
                    myn[idx] = n;
                } else {  // statistically rare overflow: handle inline
                    float s = __ldg(labels + ((size_t)b * NN + n) * CC + c);
                    sk[slotbase + idx] = pack_key(s, (unsigned)n);
                }
                idx++;
            }
        }
        const int kk = min(idx, 12);
        float sv[12];
#pragma unroll
        for (int q = 0; q < 12; q++)
            if (q < kk)
                sv[q] = __ldg(labels + ((size_t)b * NN + myn[q]) * CC + c);
#pragma unroll
        for (int q = 0; q < 12; q++)
            if (q < kk)
                sk[slotbase + q] = pack_key(sv[q], (unsigned)myn[q]);
    } else {
        // Exact fallback (statistically never taken): histogram two-pass.
        // hist aliases sk; phase-2 key writes happen after cut is latched.
        for (int i = tid; i < 1024; i += 128) hist[i] = 0;
        if (tid == 0) s_count = 0;
        __syncthreads();

        const float*         Lcol = labels + (size_t)b * NN * CC + c;
        const unsigned char* Mb   = g_mask + (size_t)b * NN;

        for (int n = tid; n < NN; n += 128) {
            if (Mb[n]) {
                float s = Lcol[(size_t)n * CC];
                if (s > 0.0f)
                    atomicAdd(&hist[min((int)(s * 1024.0f), 1023)], 1);
            }
        }
        __syncthreads();
        if (tid == 0) {
            int cum = 0, cut = 0;
            for (int bin = 1023; bin >= 0; bin--) {
                cum += hist[bin];
                if (cum >= KCAND) { cut = bin; break; }
            }
            s_cut = cut;
        }
        __syncthreads();
        const int fcut = s_cut;
        __syncthreads();                      // hist reads done before reuse
        for (int n = tid; n < NN; n += 128) {
            if (Mb[n]) {
                float s = Lcol[(size_t)n * CC];
                if (s > 0.0f && min((int)(s * 1024.0f), 1023) >= fcut) {
                    int p = atomicAdd(&s_count, 1);
                    if (p < 512)
                        sk[p] = pack_key(s, (unsigned)n);
                }
            }
        }
        __syncthreads();
        cnt = s_count;
    }
    __syncthreads();

    const int mn = min(cnt, 512);
    for (int i = mn + tid; i < 512; i += 128) sk[i] = 0ULL;
    __syncthreads();

    // Sort only the active runs (others are all-zero already)
    const int nruns = (mn + 31) >> 5;
#pragma unroll
    for (int r = 0; r < 4; r++) {
        const int run = wid * 4 + r;
        if (run < nruns) {
            unsigned long long k = sk[run * 32 + lane];
            k = warpsort32_desc(k, lane);
            sk[run * 32 + lane] = k;
        }
    }
    __syncthreads();

    // Lazy prefetch: only the top PD boxes of each active run
    if (tid < nruns * PD) {
        const int run = tid / PD;
        const int d   = tid - run * PD;
        unsigned long long k = sk[run * 32 + d];
        if (k) {
            unsigned n = 16383u - (unsigned)((k >> 9) & 0x3FFFu);
            sbox[tid] = g_boxes[(size_t)b * NN + n];
        }
    }
    __syncthreads();

    // Warp 0: 16-way merge-pop fused with greedy NMS (exact top-200 order)
    if (wid == 0) {
        const int outbase = bc * MAXPC;
        int    head   = 0;
        int    kc     = 0;
        int    pops   = 0;
        const int maxpops = min(mn, KCAND);
        float4 mykept = make_float4(0.f, 0.f, 0.f, 0.f);

        while (pops < maxpops && kc < MAXPC) {
            unsigned long long hk = 0ULL;
            if (lane < 16 && head < 32) hk = sk[lane * 32 + head];
            // two-stage REDUX argmax (keys unique; 0 = exhausted)
            unsigned hi  = (unsigned)(hk >> 32);
            unsigned mhi = __reduce_max_sync(FULLM, hi);
            unsigned lo  = (hi == mhi) ? (unsigned)hk : 0u;
            unsigned mlo = __reduce_max_sync(FULLM, lo);
            unsigned long long bk = ((unsigned long long)mhi << 32) | mlo;
            if (bk == 0ULL) break;
            unsigned bal = __ballot_sync(FULLM, hk == bk);
            int bl = __ffs(bal) - 1;
            int hd = __shfl_sync(FULLM, head, bl);
            if (lane == bl) head++;
            pops++;

            float s = __uint_as_float(mhi);
            if (s <= 0.5f) break;               // sorted: all later smaller
            float4 cb;
            if (hd < PD) {
                cb = sbox[bl * PD + hd];        // smem broadcast (common)
            } else {                            // rare: direct L1/L2 broadcast
                unsigned n = 16383u - (unsigned)((bk >> 9) & 0x3FFFu);
                cb = g_boxes[(size_t)b * NN + n];
            }

            bool ov = (lane < kc) && (iou_f(mykept, cb) > 0.5f);
            if (!__ballot_sync(FULLM, ov)) {
                if (lane == kc) mykept = cb;
                if (lane == 0) {
                    g_cls_scores[outbase + kc] = s;
                    g_cls_boxes[outbase + kc]  = cb;
                }
                kc++;
            }
        }
        if (lane < MAXPC && lane >= kc) {
            g_cls_scores[outbase + lane] = 0.0f;
            g_cls_boxes[outbase + lane]  = make_float4(0.f, 0.f, 0.f, 0.f);
        }
    }
}

// ---------------------------------------------------------------------------
// Kernel C (proven): rank-based per-batch top-20 of 420 entries.
// ---------------------------------------------------------------------------
__global__ __launch_bounds__(448) void merge_kernel(float* __restrict__ out) {
    const int b   = blockIdx.x;
    const int tid = threadIdx.x;

    __shared__ unsigned long long ks[CC * MAXPC];   // 420 keys

    float s = 0.0f;
    if (tid < CC * MAXPC) {
        s = g_cls_scores[b * CC * MAXPC + tid];
        ks[tid] = ((unsigned long long)__float_as_uint(s) << 16)
                  | (unsigned long long)(1023 - tid);
    }
    __syncthreads();

    if (tid < CC * MAXPC) {
        const unsigned long long myk = ks[tid];
        int rank = 0;
#pragma unroll 4
        for (int j = 0; j < CC * MAXPC; j++)
            rank += (ks[j] > myk);

        if (rank < MAXTOT) {
            float4 bx  = make_float4(0.f, 0.f, 0.f, 0.f);
            float  lab = 0.0f;
            if (s > 0.0f) {
                bx = g_cls_boxes[b * CC * MAXPC + tid];
                bx.x = fminf(fmaxf(bx.x, 0.0f), 1.0f);
                bx.y = fminf(fmaxf(bx.y, 0.0f), 1.0f);
                bx.z = fminf(fmaxf(bx.z, 0.0f), 1.0f);
                bx.w = fminf(fmaxf(bx.w, 0.0f), 1.0f);
                lab = (float)(tid / MAXPC);
            }
            float* ob = out + (size_t)b * MAXTOT * 4;
            float* ov = out + (size_t)BB * MAXTOT * 4 + (size_t)b * MAXTOT;
            float* ol = out + (size_t)BB * MAXTOT * 4 + (size_t)BB * MAXTOT
                            + (size_t)b * MAXTOT;
            ob[rank * 4 + 0] = bx.x;
            ob[rank * 4 + 1] = bx.y;
            ob[rank * 4 + 2] = bx.z;
            ob[rank * 4 + 3] = bx.w;
            ov[rank] = s;
            ol[rank] = lab;
        }
    }
}

// ---------------------------------------------------------------------------
extern "C" void kernel_launch(void* const* d_in, const int* in_sizes, int n_in,
                              void* d_out, int out_size) {
    const float* deltas  = (const float*)d_in[0];  // (64, 8732, 4)
    const float* labels  = (const float*)d_in[1];  // (64, 8732, 21)
    const float* anchors = (const float*)d_in[2];  // (8732, 4)
    float* out = (float*)d_out;

    decode_kernel<<<BB * BPB, DB>>>(deltas, labels, anchors);
    nms_kernel<<<BB * CC, 128>>>(labels);
    merge_kernel<<<BB, 448>>>(out);
}